// round 12
// baseline (speedup 1.0000x reference)
#include <cuda_runtime.h>
#include <cuda_fp16.h>
#include <math.h>

#define NN 50000
#define EE 800000
#define FIN 128
#define FOUT 128   // HEADS*C_OUT
#define HEADS 4
#define COUT 32
#define NEG_SLOPE 0.2f

#define SCAN_BLOCKS 196       // ceil(50000/256); chunk = 256 nodes

// ---------------- scratch (device globals; no allocation) ----------------
__device__ __align__(16) __half g_hh[NN * FOUT];      // fp16 projected features
__device__ __align__(16) float g_asrc[NN * HEADS];    // per-node src logits
__device__ __align__(16) float g_adst[NN * HEADS];    // per-node dst logits
__device__ __align__(16) __half g_Wfh[FIN * FOUT];    // permuted fp16 W fragments (32KB)
__device__ __align__(16) uint4 g_epk[EE];             // packed {src, alpha01, alpha23, pad}
__device__ int g_deg[NN];
__device__ int g_off[NN];
__device__ int g_cur[NN];
__device__ int g_csum[SCAN_BLOCKS];   // per-256-node-chunk edge counts

// ---------------- fp16 mma helper ----------------------------------------
__device__ __forceinline__ void mma_f16(float* d, const unsigned* a, const unsigned* b) {
    asm("mma.sync.aligned.m16n8k16.row.col.f32.f16.f16.f32 "
        "{%0,%1,%2,%3},{%4,%5,%6,%7},{%8,%9},{%0,%1,%2,%3};"
        : "+f"(d[0]), "+f"(d[1]), "+f"(d[2]), "+f"(d[3])
        : "r"(a[0]), "r"(a[1]), "r"(a[2]), "r"(a[3]), "r"(b[0]), "r"(b[1]));
}

// ---------------- W fragment permute (fp16) + zeroing ---------------------
// m16n8k16 B frag (k16 x n8, K-major): lane = nn*4 + ((kk&7)>>1), reg = kk>>3,
// half-pos = kk&1. half index = ((ki*16+ni)*64 + lane*2 + reg)*2 + pos
__global__ void wperm_zero_kernel(const float* __restrict__ W) {
    int i = blockIdx.x * blockDim.x + threadIdx.x;
    if (i < FIN * FOUT) {
        int k = i >> 7, n = i & 127;
        int ki = k >> 4, kk = k & 15;
        int ni = n >> 3, nn = n & 7;
        int lane = nn * 4 + ((kk & 7) >> 1);
        int reg  = kk >> 3;
        int pos  = kk & 1;
        g_Wfh[((ki * 16 + ni) * 64 + lane * 2 + reg) * 2 + pos] =
            __float2half_rn(W[k * FOUT + n]);
    }
    if (i < NN) g_deg[i] = 0;
    if (i < SCAN_BLOCKS) g_csum[i] = 0;
}

// ---------------- CSR build ----------------------------------------------
// edges are INT32 (JAX x64 disabled). layout: edges[0:EE]=src, edges[EE:2EE]=dst
__global__ void hist_kernel(const int* __restrict__ edges) {
    int t = blockIdx.x * blockDim.x + threadIdx.x;
    if (t < EE / 2) {
        int2 d = ((const int2*)(edges + EE))[t];
        atomicAdd(&g_deg[d.x], 1);
        atomicAdd(&g_deg[d.y], 1);
        atomicAdd(&g_csum[d.x >> 8], 1);
        atomicAdd(&g_csum[d.y >> 8], 1);
    }
}

// ---------------- single-launch scan --------------------------------------
// Each block: (a) redundantly scans the 196 chunk sums -> its global prefix,
// (b) local scan of its 256 degrees. No cross-block waiting.
__global__ void scan_kernel() {
    __shared__ int s1[256];
    __shared__ int swarp[8];
    const int tid = threadIdx.x, bid = blockIdx.x;
    const int lane = tid & 31, w = tid >> 5;

    // ---- chunk-sum inclusive scan (256-wide, entries >=196 are 0)
    int c = (tid < SCAN_BLOCKS) ? g_csum[tid] : 0;
    int xc = c;
#pragma unroll
    for (int d = 1; d < 32; d <<= 1) {
        int y = __shfl_up_sync(0xffffffffu, xc, d);
        if (lane >= d) xc += y;
    }
    if (lane == 31) swarp[w] = xc;
    __syncthreads();
    if (w == 0) {
        int ws = (lane < 8) ? swarp[lane] : 0;
#pragma unroll
        for (int d = 1; d < 8; d <<= 1) {
            int y = __shfl_up_sync(0xffffffffu, ws, d);
            if (lane >= d) ws += y;
        }
        if (lane < 8) swarp[lane] = ws;
    }
    __syncthreads();
    s1[tid] = xc + ((w > 0) ? swarp[w - 1] : 0);   // inclusive
    __syncthreads();
    const int prefix = (bid > 0) ? s1[bid - 1] : 0;
    __syncthreads();

    // ---- local degree scan
    int gt = bid * 256 + tid;
    int v = (gt < NN) ? g_deg[gt] : 0;
    int xv = v;
#pragma unroll
    for (int d = 1; d < 32; d <<= 1) {
        int y = __shfl_up_sync(0xffffffffu, xv, d);
        if (lane >= d) xv += y;
    }
    if (lane == 31) swarp[w] = xv;
    __syncthreads();
    if (w == 0) {
        int ws = (lane < 8) ? swarp[lane] : 0;
#pragma unroll
        for (int d = 1; d < 8; d <<= 1) {
            int y = __shfl_up_sync(0xffffffffu, ws, d);
            if (lane >= d) ws += y;
        }
        if (lane < 8) swarp[lane] = ws;
    }
    __syncthreads();
    int excl = xv - v + ((w > 0) ? swarp[w - 1] : 0) + prefix;
    if (gt < NN) {
        g_off[gt] = excl;
        g_cur[gt] = excl;
    }
}

// ---------------- fp16 GEMM + fused attention logits (R10, known-good) ----
// Block: 64 rows x 128 cols, 512 threads (16 warps), 2 CTAs/SM.
#define A_STRIDE_H 136                       // halfs; 272B rows, conflict-free
#define GEMM_SMEM_BYTES (64 * A_STRIDE_H * 2)  // 17.4KB

__global__ void __launch_bounds__(512, 2) gemm_a_kernel(
        const float* __restrict__ x,
        const float* __restrict__ att_src, const float* __restrict__ att_dst) {
    extern __shared__ __align__(16) __half sAh[];   // 64 x 136 halfs

    const int tid = threadIdx.x;
    const int rowBase = blockIdx.x * 64;

    // ---- stage A: load fp32, convert to fp16
#pragma unroll
    for (int j = 0; j < 4; j++) {
        int idx4 = tid + j * 512;          // 0..2047
        int r = idx4 >> 5;
        int c0 = (idx4 & 31) * 4;
        int gr = rowBase + r;
        float4 v = (gr < NN) ? *(const float4*)&x[gr * FIN + c0]
                             : make_float4(0.f, 0.f, 0.f, 0.f);
        __half2 h0 = __floats2half2_rn(v.x, v.y);
        __half2 h1 = __floats2half2_rn(v.z, v.w);
        uint2 pk;
        pk.x = *(unsigned*)&h0;
        pk.y = *(unsigned*)&h1;
        *(uint2*)&sAh[r * A_STRIDE_H + c0] = pk;
    }
    __syncthreads();

    const int wid = tid >> 5, lane = tid & 31;
    const int mi = wid & 3;
    const int ng = wid >> 2;        // head index, n-tiles ng*4 .. ng*4+3
    const int lr = lane >> 2;
    const int lc = lane & 3;

    float acc[4][4];
#pragma unroll
    for (int nj = 0; nj < 4; nj++)
#pragma unroll
        for (int c = 0; c < 4; c++) acc[nj][c] = 0.f;

    const int r = mi * 16 + lr;
#pragma unroll
    for (int ki = 0; ki < 8; ki++) {
        int kb = ki * 16;
        unsigned a[4];
        a[0] = *(const unsigned*)&sAh[r * A_STRIDE_H + kb + 2 * lc];
        a[1] = *(const unsigned*)&sAh[(r + 8) * A_STRIDE_H + kb + 2 * lc];
        a[2] = *(const unsigned*)&sAh[r * A_STRIDE_H + kb + 2 * lc + 8];
        a[3] = *(const unsigned*)&sAh[(r + 8) * A_STRIDE_H + kb + 2 * lc + 8];
#pragma unroll
        for (int nj = 0; nj < 4; nj++) {
            uint2 b2 = __ldg((const uint2*)&g_Wfh[((ki * 16 + ng * 4 + nj) * 64 + lane * 2) * 2]);
            unsigned b[2] = {b2.x, b2.y};
            mma_f16(acc[nj], a, b);
        }
    }

    // ---- epilogue 1: fp16 h stores
    const int r0 = rowBase + mi * 16 + lr;
    const int r1 = r0 + 8;
#pragma unroll
    for (int nj = 0; nj < 4; nj++) {
        int col0 = (ng * 4 + nj) * 8 + lc * 2;
        if (r0 < NN) *(__half2*)&g_hh[r0 * FOUT + col0] = __floats2half2_rn(acc[nj][0], acc[nj][1]);
        if (r1 < NN) *(__half2*)&g_hh[r1 * FOUT + col0] = __floats2half2_rn(acc[nj][2], acc[nj][3]);
    }

    // ---- epilogue 2: fused attention logits (this warp = head ng)
    float ps[2] = {0.f, 0.f};   // [row-half]
    float pd[2] = {0.f, 0.f};
#pragma unroll
    for (int nj = 0; nj < 4; nj++) {
        int col0 = (ng * 4 + nj) * 8 + lc * 2;
        float a0 = att_src[col0], a1 = att_src[col0 + 1];
        float d0 = att_dst[col0], d1 = att_dst[col0 + 1];
        ps[0] += acc[nj][0] * a0 + acc[nj][1] * a1;
        ps[1] += acc[nj][2] * a0 + acc[nj][3] * a1;
        pd[0] += acc[nj][0] * d0 + acc[nj][1] * d1;
        pd[1] += acc[nj][2] * d0 + acc[nj][3] * d1;
    }
#pragma unroll
    for (int ch = 0; ch < 2; ch++) {
#pragma unroll
        for (int d = 1; d <= 2; d <<= 1) {
            ps[ch] += __shfl_xor_sync(0xffffffffu, ps[ch], d);
            pd[ch] += __shfl_xor_sync(0xffffffffu, pd[ch], d);
        }
    }
    if (lc == 0) {
#pragma unroll
        for (int ch = 0; ch < 2; ch++) {
            int rr = rowBase + mi * 16 + lr + ch * 8;
            if (rr < NN) {
                g_asrc[rr * HEADS + ng] = ps[ch];
                g_adst[rr * HEADS + ng] = pd[ch];
            }
        }
    }
}

// ---------------- scatter + packed per-edge record ------------------------
// record = {src, alpha01(fp16x2), alpha23(fp16x2), 0} in one STG.128
__global__ void scatter_alpha_kernel(const int* __restrict__ edges) {
    int t = blockIdx.x * blockDim.x + threadIdx.x;
    if (t >= EE / 4) return;
    int4 s4 = ((const int4*)edges)[t];
    int4 d4 = ((const int4*)(edges + EE))[t];
    int ss[4] = {s4.x, s4.y, s4.z, s4.w};
    int dd[4] = {d4.x, d4.y, d4.z, d4.w};
#pragma unroll
    for (int q = 0; q < 4; q++) {
        int s = ss[q], d = dd[q];
        float4 as = *(const float4*)&g_asrc[s * HEADS];
        float4 ad = *(const float4*)&g_adst[d * HEADS];
        float e0 = as.x + ad.x, e1 = as.y + ad.y, e2 = as.z + ad.z, e3 = as.w + ad.w;
        e0 = (e0 > 0.f) ? e0 : NEG_SLOPE * e0;
        e1 = (e1 > 0.f) ? e1 : NEG_SLOPE * e1;
        e2 = (e2 > 0.f) ? e2 : NEG_SLOPE * e2;
        e3 = (e3 > 0.f) ? e3 : NEG_SLOPE * e3;
        __half2 p0 = __floats2half2_rn(__expf(e0), __expf(e1));
        __half2 p1 = __floats2half2_rn(__expf(e2), __expf(e3));
        int pos = atomicAdd(&g_cur[d], 1);
        uint4 rec;
        rec.x = (unsigned)s;
        rec.y = *(unsigned*)&p0;
        rec.z = *(unsigned*)&p1;
        rec.w = 0;
        g_epk[pos] = rec;
    }
}

// ---------------- GAT aggregate: single pass, warp per dst ----------------
__global__ void __launch_bounds__(256) gat_kernel(
        const float* __restrict__ bias, float* __restrict__ out) {
    __shared__ __align__(16) float s_al[8][32][4];
    __shared__ int s_src[8][32];

    const int w = threadIdx.x >> 5;
    const int lane = threadIdx.x & 31;
    const int n = blockIdx.x * 8 + w;
    if (n >= NN) return;

    const int start = g_off[n];
    const int deg   = g_deg[n];
    const int lane4 = lane * 4;
    float4 bv = *(const float4*)&bias[lane4];

    if (deg == 0) {
        *(float4*)&out[n * FOUT + lane4] = bv;
        return;
    }

    const int hl = lane >> 3;
    float4 acc = make_float4(0.f, 0.f, 0.f, 0.f);
    float dacc = 0.f;   // denominator for this lane's head

    for (int base = 0; base < deg; base += 32) {
        int i = base + lane;
        if (i < deg) {
            uint4 rec = g_epk[start + i];     // one LDG.128 per edge
            s_src[w][lane] = (int)rec.x;
            float2 a0 = __half22float2(*(__half2*)&rec.y);
            float2 a1 = __half22float2(*(__half2*)&rec.z);
            s_al[w][lane][0] = a0.x;
            s_al[w][lane][1] = a0.y;
            s_al[w][lane][2] = a1.x;
            s_al[w][lane][3] = a1.y;
        }
        __syncwarp();

        int cnt = min(32, deg - base);
#pragma unroll 8
        for (int j = 0; j < cnt; j++) {
            int sj = s_src[w][j];
            float ex = s_al[w][j][hl];
            dacc += ex;
            uint2 u = *(const uint2*)&g_hh[sj * FOUT + lane4];   // 256B/warp
            float2 f0 = __half22float2(*(__half2*)&u.x);
            float2 f1 = __half22float2(*(__half2*)&u.y);
            acc.x += ex * f0.x;
            acc.y += ex * f0.y;
            acc.z += ex * f1.x;
            acc.w += ex * f1.y;
        }
        __syncwarp();
    }
    float invd = 1.f / fmaxf(dacc, 1e-16f);
    acc.x = acc.x * invd + bv.x;
    acc.y = acc.y * invd + bv.y;
    acc.z = acc.z * invd + bv.z;
    acc.w = acc.w * invd + bv.w;
    *(float4*)&out[n * FOUT + lane4] = acc;
}

// ---------------- launch --------------------------------------------------
extern "C" void kernel_launch(void* const* d_in, const int* in_sizes, int n_in,
                              void* d_out, int out_size) {
    const float* x       = (const float*)d_in[0];
    const int*   edges   = (const int*)d_in[1];    // int32! (JAX x64 disabled)
    const float* W       = (const float*)d_in[2];
    const float* att_src = (const float*)d_in[3];
    const float* att_dst = (const float*)d_in[4];
    const float* bias    = (const float*)d_in[5];
    float*       out     = (float*)d_out;

    cudaFuncSetAttribute(gemm_a_kernel,
                         cudaFuncAttributeMaxDynamicSharedMemorySize, GEMM_SMEM_BYTES);

    wperm_zero_kernel<<<196, 256>>>(W);
    hist_kernel<<<(EE / 2 + 255) / 256, 256>>>(edges);
    scan_kernel<<<SCAN_BLOCKS, 256>>>();
    gemm_a_kernel<<<(NN + 63) / 64, 512, GEMM_SMEM_BYTES>>>(x, att_src, att_dst);  // launch #4 -> profiled
    scatter_alpha_kernel<<<(EE / 4 + 255) / 256, 256>>>(edges);
    gat_kernel<<<(NN + 7) / 8, 256>>>(bias, out);
}

// round 13
// speedup vs baseline: 2.2157x; 2.2157x over previous
#include <cuda_runtime.h>
#include <cuda_fp16.h>
#include <math.h>

#define NN 50000
#define EE 800000
#define FIN 128
#define FOUT 128   // HEADS*C_OUT
#define HEADS 4
#define COUT 32
#define NEG_SLOPE 0.2f

#define SCAN_BLOCKS 196   // ceil(50000/256)

// ---------------- scratch (device globals; no allocation) ----------------
__device__ __align__(16) __half g_hh[NN * FOUT];      // fp16 projected features
__device__ __align__(16) float g_asrc[NN * HEADS];    // per-node src logits
__device__ __align__(16) float g_adst[NN * HEADS];    // per-node dst logits
__device__ __align__(16) __half g_Wfh[FIN * FOUT];    // permuted fp16 W fragments (32KB)
__device__ __align__(16) uint4 g_epk[EE];             // packed {src, alpha01, alpha23, pad}
__device__ int g_deg[NN];
__device__ int g_off[NN];
__device__ int g_cur[NN];
__device__ int g_bsum[SCAN_BLOCKS];

// ---------------- fp16 mma helper ----------------------------------------
__device__ __forceinline__ void mma_f16(float* d, const unsigned* a, const unsigned* b) {
    asm("mma.sync.aligned.m16n8k16.row.col.f32.f16.f16.f32 "
        "{%0,%1,%2,%3},{%4,%5,%6,%7},{%8,%9},{%0,%1,%2,%3};"
        : "+f"(d[0]), "+f"(d[1]), "+f"(d[2]), "+f"(d[3])
        : "r"(a[0]), "r"(a[1]), "r"(a[2]), "r"(a[3]), "r"(b[0]), "r"(b[1]));
}

// ---------------- W fragment permute (fp16) + degree zero -----------------
// m16n8k16 B frag (k16 x n8, K-major): lane = nn*4 + ((kk&7)>>1), reg = kk>>3,
// half-pos = kk&1. half index = ((ki*16+ni)*64 + lane*2 + reg)*2 + pos
__global__ void wperm_zero_kernel(const float* __restrict__ W) {
    int i = blockIdx.x * blockDim.x + threadIdx.x;
    if (i < FIN * FOUT) {
        int k = i >> 7, n = i & 127;
        int ki = k >> 4, kk = k & 15;
        int ni = n >> 3, nn = n & 7;
        int lane = nn * 4 + ((kk & 7) >> 1);
        int reg  = kk >> 3;
        int pos  = kk & 1;
        g_Wfh[((ki * 16 + ni) * 64 + lane * 2 + reg) * 2 + pos] =
            __float2half_rn(W[k * FOUT + n]);
    }
    if (i < NN) g_deg[i] = 0;
}

// ---------------- CSR build ----------------------------------------------
// edges are INT32 (JAX x64 disabled). layout: edges[0:EE]=src, edges[EE:2EE]=dst
// NOTE: NO chunk-counter atomics here — 196-address atomics serialize on ~6
// LTS slices and cost ~100us (R11/R12 post-mortem).
__global__ void hist_kernel(const int* __restrict__ edges) {
    int t = blockIdx.x * blockDim.x + threadIdx.x;
    if (t < EE / 2) {
        int2 d = ((const int2*)(edges + EE))[t];
        atomicAdd(&g_deg[d.x], 1);
        atomicAdd(&g_deg[d.y], 1);
    }
}

// scan1: block-local exclusive scan of degrees; block totals to g_bsum
__global__ void scan1_kernel() {
    __shared__ int swarp[8];
    int tid = threadIdx.x, bid = blockIdx.x;
    int gt = bid * 256 + tid;
    int lane = tid & 31, w = tid >> 5;

    int v = (gt < NN) ? g_deg[gt] : 0;
    int x = v;
#pragma unroll
    for (int d = 1; d < 32; d <<= 1) {
        int y = __shfl_up_sync(0xffffffffu, x, d);
        if (lane >= d) x += y;
    }
    if (lane == 31) swarp[w] = x;
    __syncthreads();
    if (w == 0) {
        int ws = (lane < 8) ? swarp[lane] : 0;
#pragma unroll
        for (int d = 1; d < 8; d <<= 1) {
            int y = __shfl_up_sync(0xffffffffu, ws, d);
            if (lane >= d) ws += y;
        }
        if (lane < 8) swarp[lane] = ws;
    }
    __syncthreads();
    int excl = x - v + ((w > 0) ? swarp[w - 1] : 0);
    if (gt < NN) g_off[gt] = excl;
    if (tid == 255) g_bsum[bid] = excl + v;
}

// scan2: every block redundantly prefixes g_bsum, adds to its local offsets
__global__ void scan2_kernel() {
    __shared__ int sb[SCAN_BLOCKS];
    __shared__ int sprefix;
    int tid = threadIdx.x, bid = blockIdx.x;
    if (tid < SCAN_BLOCKS) sb[tid] = g_bsum[tid];
    __syncthreads();
    if (tid == 0) {
        int run = 0;
        for (int i = 0; i < bid; i++) run += sb[i];
        sprefix = run;
    }
    __syncthreads();
    int gt = bid * 256 + tid;
    if (gt < NN) {
        int o = g_off[gt] + sprefix;
        g_off[gt] = o;
        g_cur[gt] = o;
    }
}

// ---------------- fp16 GEMM + fused attention logits (R10, known-good) ----
// Block: 64 rows x 128 cols, 512 threads (16 warps), 2 CTAs/SM.
#define A_STRIDE_H 136                       // halfs; 272B rows, conflict-free
#define GEMM_SMEM_BYTES (64 * A_STRIDE_H * 2)  // 17.4KB

__global__ void __launch_bounds__(512, 2) gemm_a_kernel(
        const float* __restrict__ x,
        const float* __restrict__ att_src, const float* __restrict__ att_dst) {
    extern __shared__ __align__(16) __half sAh[];   // 64 x 136 halfs

    const int tid = threadIdx.x;
    const int rowBase = blockIdx.x * 64;

    // ---- stage A: load fp32, convert to fp16
#pragma unroll
    for (int j = 0; j < 4; j++) {
        int idx4 = tid + j * 512;          // 0..2047
        int r = idx4 >> 5;
        int c0 = (idx4 & 31) * 4;
        int gr = rowBase + r;
        float4 v = (gr < NN) ? *(const float4*)&x[gr * FIN + c0]
                             : make_float4(0.f, 0.f, 0.f, 0.f);
        __half2 h0 = __floats2half2_rn(v.x, v.y);
        __half2 h1 = __floats2half2_rn(v.z, v.w);
        uint2 pk;
        pk.x = *(unsigned*)&h0;
        pk.y = *(unsigned*)&h1;
        *(uint2*)&sAh[r * A_STRIDE_H + c0] = pk;
    }
    __syncthreads();

    const int wid = tid >> 5, lane = tid & 31;
    const int mi = wid & 3;
    const int ng = wid >> 2;        // head index, n-tiles ng*4 .. ng*4+3
    const int lr = lane >> 2;
    const int lc = lane & 3;

    float acc[4][4];
#pragma unroll
    for (int nj = 0; nj < 4; nj++)
#pragma unroll
        for (int c = 0; c < 4; c++) acc[nj][c] = 0.f;

    const int r = mi * 16 + lr;
#pragma unroll
    for (int ki = 0; ki < 8; ki++) {
        int kb = ki * 16;
        unsigned a[4];
        a[0] = *(const unsigned*)&sAh[r * A_STRIDE_H + kb + 2 * lc];
        a[1] = *(const unsigned*)&sAh[(r + 8) * A_STRIDE_H + kb + 2 * lc];
        a[2] = *(const unsigned*)&sAh[r * A_STRIDE_H + kb + 2 * lc + 8];
        a[3] = *(const unsigned*)&sAh[(r + 8) * A_STRIDE_H + kb + 2 * lc + 8];
#pragma unroll
        for (int nj = 0; nj < 4; nj++) {
            uint2 b2 = __ldg((const uint2*)&g_Wfh[((ki * 16 + ng * 4 + nj) * 64 + lane * 2) * 2]);
            unsigned b[2] = {b2.x, b2.y};
            mma_f16(acc[nj], a, b);
        }
    }

    // ---- epilogue 1: fp16 h stores
    const int r0 = rowBase + mi * 16 + lr;
    const int r1 = r0 + 8;
#pragma unroll
    for (int nj = 0; nj < 4; nj++) {
        int col0 = (ng * 4 + nj) * 8 + lc * 2;
        if (r0 < NN) *(__half2*)&g_hh[r0 * FOUT + col0] = __floats2half2_rn(acc[nj][0], acc[nj][1]);
        if (r1 < NN) *(__half2*)&g_hh[r1 * FOUT + col0] = __floats2half2_rn(acc[nj][2], acc[nj][3]);
    }

    // ---- epilogue 2: fused attention logits (this warp = head ng)
    float ps[2] = {0.f, 0.f};   // [row-half]
    float pd[2] = {0.f, 0.f};
#pragma unroll
    for (int nj = 0; nj < 4; nj++) {
        int col0 = (ng * 4 + nj) * 8 + lc * 2;
        float a0 = att_src[col0], a1 = att_src[col0 + 1];
        float d0 = att_dst[col0], d1 = att_dst[col0 + 1];
        ps[0] += acc[nj][0] * a0 + acc[nj][1] * a1;
        ps[1] += acc[nj][2] * a0 + acc[nj][3] * a1;
        pd[0] += acc[nj][0] * d0 + acc[nj][1] * d1;
        pd[1] += acc[nj][2] * d0 + acc[nj][3] * d1;
    }
#pragma unroll
    for (int ch = 0; ch < 2; ch++) {
#pragma unroll
        for (int d = 1; d <= 2; d <<= 1) {
            ps[ch] += __shfl_xor_sync(0xffffffffu, ps[ch], d);
            pd[ch] += __shfl_xor_sync(0xffffffffu, pd[ch], d);
        }
    }
    if (lc == 0) {
#pragma unroll
        for (int ch = 0; ch < 2; ch++) {
            int rr = rowBase + mi * 16 + lr + ch * 8;
            if (rr < NN) {
                g_asrc[rr * HEADS + ng] = ps[ch];
                g_adst[rr * HEADS + ng] = pd[ch];
            }
        }
    }
}

// ---------------- scatter + packed per-edge record ------------------------
// record = {src, alpha01(fp16x2), alpha23(fp16x2), 0} in one STG.128
__global__ void scatter_alpha_kernel(const int* __restrict__ edges) {
    int t = blockIdx.x * blockDim.x + threadIdx.x;
    if (t >= EE / 4) return;
    int4 s4 = ((const int4*)edges)[t];
    int4 d4 = ((const int4*)(edges + EE))[t];
    int ss[4] = {s4.x, s4.y, s4.z, s4.w};
    int dd[4] = {d4.x, d4.y, d4.z, d4.w};
#pragma unroll
    for (int q = 0; q < 4; q++) {
        int s = ss[q], d = dd[q];
        float4 as = *(const float4*)&g_asrc[s * HEADS];
        float4 ad = *(const float4*)&g_adst[d * HEADS];
        float e0 = as.x + ad.x, e1 = as.y + ad.y, e2 = as.z + ad.z, e3 = as.w + ad.w;
        e0 = (e0 > 0.f) ? e0 : NEG_SLOPE * e0;
        e1 = (e1 > 0.f) ? e1 : NEG_SLOPE * e1;
        e2 = (e2 > 0.f) ? e2 : NEG_SLOPE * e2;
        e3 = (e3 > 0.f) ? e3 : NEG_SLOPE * e3;
        __half2 p0 = __floats2half2_rn(__expf(e0), __expf(e1));
        __half2 p1 = __floats2half2_rn(__expf(e2), __expf(e3));
        int pos = atomicAdd(&g_cur[d], 1);
        uint4 rec;
        rec.x = (unsigned)s;
        rec.y = *(unsigned*)&p0;
        rec.z = *(unsigned*)&p1;
        rec.w = 0;
        g_epk[pos] = rec;
    }
}

// ---------------- GAT aggregate: single pass, warp per dst ----------------
__global__ void __launch_bounds__(256) gat_kernel(
        const float* __restrict__ bias, float* __restrict__ out) {
    __shared__ __align__(16) float s_al[8][32][4];
    __shared__ int s_src[8][32];

    const int w = threadIdx.x >> 5;
    const int lane = threadIdx.x & 31;
    const int n = blockIdx.x * 8 + w;
    if (n >= NN) return;

    const int start = g_off[n];
    const int deg   = g_deg[n];
    const int lane4 = lane * 4;
    float4 bv = *(const float4*)&bias[lane4];

    if (deg == 0) {
        *(float4*)&out[n * FOUT + lane4] = bv;
        return;
    }

    const int hl = lane >> 3;
    float4 acc = make_float4(0.f, 0.f, 0.f, 0.f);
    float dacc = 0.f;   // denominator for this lane's head

    for (int base = 0; base < deg; base += 32) {
        int i = base + lane;
        if (i < deg) {
            uint4 rec = g_epk[start + i];     // one LDG.128 per edge
            s_src[w][lane] = (int)rec.x;
            float2 a0 = __half22float2(*(__half2*)&rec.y);
            float2 a1 = __half22float2(*(__half2*)&rec.z);
            s_al[w][lane][0] = a0.x;
            s_al[w][lane][1] = a0.y;
            s_al[w][lane][2] = a1.x;
            s_al[w][lane][3] = a1.y;
        }
        __syncwarp();

        int cnt = min(32, deg - base);
#pragma unroll 8
        for (int j = 0; j < cnt; j++) {
            int sj = s_src[w][j];
            float ex = s_al[w][j][hl];
            dacc += ex;
            uint2 u = *(const uint2*)&g_hh[sj * FOUT + lane4];   // 256B/warp
            float2 f0 = __half22float2(*(__half2*)&u.x);
            float2 f1 = __half22float2(*(__half2*)&u.y);
            acc.x += ex * f0.x;
            acc.y += ex * f0.y;
            acc.z += ex * f1.x;
            acc.w += ex * f1.y;
        }
        __syncwarp();
    }
    float invd = 1.f / fmaxf(dacc, 1e-16f);
    acc.x = acc.x * invd + bv.x;
    acc.y = acc.y * invd + bv.y;
    acc.z = acc.z * invd + bv.z;
    acc.w = acc.w * invd + bv.w;
    *(float4*)&out[n * FOUT + lane4] = acc;
}

// ---------------- launch --------------------------------------------------
extern "C" void kernel_launch(void* const* d_in, const int* in_sizes, int n_in,
                              void* d_out, int out_size) {
    const float* x       = (const float*)d_in[0];
    const int*   edges   = (const int*)d_in[1];    // int32! (JAX x64 disabled)
    const float* W       = (const float*)d_in[2];
    const float* att_src = (const float*)d_in[3];
    const float* att_dst = (const float*)d_in[4];
    const float* bias    = (const float*)d_in[5];
    float*       out     = (float*)d_out;

    cudaFuncSetAttribute(gemm_a_kernel,
                         cudaFuncAttributeMaxDynamicSharedMemorySize, GEMM_SMEM_BYTES);

    wperm_zero_kernel<<<196, 256>>>(W);
    hist_kernel<<<(EE / 2 + 255) / 256, 256>>>(edges);
    scan1_kernel<<<SCAN_BLOCKS, 256>>>();
    gemm_a_kernel<<<(NN + 63) / 64, 512, GEMM_SMEM_BYTES>>>(x, att_src, att_dst);  // launch #4 -> profiled
    scan2_kernel<<<SCAN_BLOCKS, 256>>>();
    scatter_alpha_kernel<<<(EE / 4 + 255) / 256, 256>>>(edges);
    gat_kernel<<<(NN + 7) / 8, 256>>>(bias, out);
}

// round 14
// speedup vs baseline: 2.2727x; 1.0258x over previous
#include <cuda_runtime.h>
#include <cuda_fp16.h>
#include <math.h>

#define NN 50000
#define EE 800000
#define FIN 128
#define FOUT 128   // HEADS*C_OUT
#define HEADS 4
#define COUT 32
#define NEG_SLOPE 0.2f

#define SCAN_BLOCKS 196   // ceil(50000/256)

// ---------------- scratch (device globals; no allocation) ----------------
__device__ __align__(16) __half g_hh[NN * FOUT];      // fp16 projected features
__device__ __align__(16) float g_asrc[NN * HEADS];    // per-node src logits
__device__ __align__(16) float g_adst[NN * HEADS];    // per-node dst logits
__device__ __align__(16) __half g_Wfh[FIN * FOUT];    // permuted fp16 W fragments (32KB)
__device__ __align__(16) uint4 g_epk[EE];             // packed {src, alpha01, alpha23, pad}
__device__ int g_deg[NN];
__device__ int g_off[NN];
__device__ int g_cur[NN];
__device__ int g_bsum[SCAN_BLOCKS];

// ---------------- fp16 mma helper ----------------------------------------
__device__ __forceinline__ void mma_f16(float* d, const unsigned* a, const unsigned* b) {
    asm("mma.sync.aligned.m16n8k16.row.col.f32.f16.f16.f32 "
        "{%0,%1,%2,%3},{%4,%5,%6,%7},{%8,%9},{%0,%1,%2,%3};"
        : "+f"(d[0]), "+f"(d[1]), "+f"(d[2]), "+f"(d[3])
        : "r"(a[0]), "r"(a[1]), "r"(a[2]), "r"(a[3]), "r"(b[0]), "r"(b[1]));
}

// ---------------- branch A head: zero degrees -----------------------------
__global__ void zero_kernel() {
    int i = blockIdx.x * blockDim.x + threadIdx.x;
    if (i < NN) g_deg[i] = 0;
}

// ---------------- branch B head: W fragment permute (fp16) ----------------
// m16n8k16 B frag (k16 x n8, K-major): lane = nn*4 + ((kk&7)>>1), reg = kk>>3,
// half-pos = kk&1. half index = ((ki*16+ni)*64 + lane*2 + reg)*2 + pos
__global__ void wperm_kernel(const float* __restrict__ W) {
    int i = blockIdx.x * blockDim.x + threadIdx.x;
    if (i < FIN * FOUT) {
        int k = i >> 7, n = i & 127;
        int ki = k >> 4, kk = k & 15;
        int ni = n >> 3, nn = n & 7;
        int lane = nn * 4 + ((kk & 7) >> 1);
        int reg  = kk >> 3;
        int pos  = kk & 1;
        g_Wfh[((ki * 16 + ni) * 64 + lane * 2 + reg) * 2 + pos] =
            __float2half_rn(W[k * FOUT + n]);
    }
}

// ---------------- CSR build ----------------------------------------------
// edges are INT32 (JAX x64 disabled). layout: edges[0:EE]=src, edges[EE:2EE]=dst
// NO small-array chunk atomics (196-address atomics serialize on ~6 LTS slices,
// ~100us — R11/R12 post-mortem).
__global__ void hist_kernel(const int* __restrict__ edges) {
    int t = blockIdx.x * blockDim.x + threadIdx.x;
    if (t < EE / 2) {
        int2 d = ((const int2*)(edges + EE))[t];
        atomicAdd(&g_deg[d.x], 1);
        atomicAdd(&g_deg[d.y], 1);
    }
}

// scan1: block-local exclusive scan of degrees; block totals to g_bsum
__global__ void scan1_kernel() {
    __shared__ int swarp[8];
    int tid = threadIdx.x, bid = blockIdx.x;
    int gt = bid * 256 + tid;
    int lane = tid & 31, w = tid >> 5;

    int v = (gt < NN) ? g_deg[gt] : 0;
    int x = v;
#pragma unroll
    for (int d = 1; d < 32; d <<= 1) {
        int y = __shfl_up_sync(0xffffffffu, x, d);
        if (lane >= d) x += y;
    }
    if (lane == 31) swarp[w] = x;
    __syncthreads();
    if (w == 0) {
        int ws = (lane < 8) ? swarp[lane] : 0;
#pragma unroll
        for (int d = 1; d < 8; d <<= 1) {
            int y = __shfl_up_sync(0xffffffffu, ws, d);
            if (lane >= d) ws += y;
        }
        if (lane < 8) swarp[lane] = ws;
    }
    __syncthreads();
    int excl = x - v + ((w > 0) ? swarp[w - 1] : 0);
    if (gt < NN) g_off[gt] = excl;
    if (tid == 255) g_bsum[bid] = excl + v;
}

// scan2: every block redundantly prefixes g_bsum, adds to its local offsets
__global__ void scan2_kernel() {
    __shared__ int sb[SCAN_BLOCKS];
    __shared__ int sprefix;
    int tid = threadIdx.x, bid = blockIdx.x;
    if (tid < SCAN_BLOCKS) sb[tid] = g_bsum[tid];
    __syncthreads();
    if (tid == 0) {
        int run = 0;
        for (int i = 0; i < bid; i++) run += sb[i];
        sprefix = run;
    }
    __syncthreads();
    int gt = bid * 256 + tid;
    if (gt < NN) {
        int o = g_off[gt] + sprefix;
        g_off[gt] = o;
        g_cur[gt] = o;
    }
}

// ---------------- fp16 GEMM + fused attention logits (known-good) ---------
// Block: 64 rows x 128 cols, 512 threads (16 warps), 2 CTAs/SM. 64 regs.
#define A_STRIDE_H 136                       // halfs; 272B rows, conflict-free
#define GEMM_SMEM_BYTES (64 * A_STRIDE_H * 2)  // 17.4KB

__global__ void __launch_bounds__(512, 2) gemm_a_kernel(
        const float* __restrict__ x,
        const float* __restrict__ att_src, const float* __restrict__ att_dst) {
    extern __shared__ __align__(16) __half sAh[];   // 64 x 136 halfs

    const int tid = threadIdx.x;
    const int rowBase = blockIdx.x * 64;

    // ---- stage A: load fp32, convert to fp16
#pragma unroll
    for (int j = 0; j < 4; j++) {
        int idx4 = tid + j * 512;          // 0..2047
        int r = idx4 >> 5;
        int c0 = (idx4 & 31) * 4;
        int gr = rowBase + r;
        float4 v = (gr < NN) ? *(const float4*)&x[gr * FIN + c0]
                             : make_float4(0.f, 0.f, 0.f, 0.f);
        __half2 h0 = __floats2half2_rn(v.x, v.y);
        __half2 h1 = __floats2half2_rn(v.z, v.w);
        uint2 pk;
        pk.x = *(unsigned*)&h0;
        pk.y = *(unsigned*)&h1;
        *(uint2*)&sAh[r * A_STRIDE_H + c0] = pk;
    }
    __syncthreads();

    const int wid = tid >> 5, lane = tid & 31;
    const int mi = wid & 3;
    const int ng = wid >> 2;        // head index, n-tiles ng*4 .. ng*4+3
    const int lr = lane >> 2;
    const int lc = lane & 3;

    float acc[4][4];
#pragma unroll
    for (int nj = 0; nj < 4; nj++)
#pragma unroll
        for (int c = 0; c < 4; c++) acc[nj][c] = 0.f;

    const int r = mi * 16 + lr;
#pragma unroll
    for (int ki = 0; ki < 8; ki++) {
        int kb = ki * 16;
        unsigned a[4];
        a[0] = *(const unsigned*)&sAh[r * A_STRIDE_H + kb + 2 * lc];
        a[1] = *(const unsigned*)&sAh[(r + 8) * A_STRIDE_H + kb + 2 * lc];
        a[2] = *(const unsigned*)&sAh[r * A_STRIDE_H + kb + 2 * lc + 8];
        a[3] = *(const unsigned*)&sAh[(r + 8) * A_STRIDE_H + kb + 2 * lc + 8];
#pragma unroll
        for (int nj = 0; nj < 4; nj++) {
            uint2 b2 = __ldg((const uint2*)&g_Wfh[((ki * 16 + ng * 4 + nj) * 64 + lane * 2) * 2]);
            unsigned b[2] = {b2.x, b2.y};
            mma_f16(acc[nj], a, b);
        }
    }

    // ---- epilogue 1: fp16 h stores
    const int r0 = rowBase + mi * 16 + lr;
    const int r1 = r0 + 8;
#pragma unroll
    for (int nj = 0; nj < 4; nj++) {
        int col0 = (ng * 4 + nj) * 8 + lc * 2;
        if (r0 < NN) *(__half2*)&g_hh[r0 * FOUT + col0] = __floats2half2_rn(acc[nj][0], acc[nj][1]);
        if (r1 < NN) *(__half2*)&g_hh[r1 * FOUT + col0] = __floats2half2_rn(acc[nj][2], acc[nj][3]);
    }

    // ---- epilogue 2: fused attention logits (this warp = head ng)
    float ps[2] = {0.f, 0.f};   // [row-half]
    float pd[2] = {0.f, 0.f};
#pragma unroll
    for (int nj = 0; nj < 4; nj++) {
        int col0 = (ng * 4 + nj) * 8 + lc * 2;
        float a0 = att_src[col0], a1 = att_src[col0 + 1];
        float d0 = att_dst[col0], d1 = att_dst[col0 + 1];
        ps[0] += acc[nj][0] * a0 + acc[nj][1] * a1;
        ps[1] += acc[nj][2] * a0 + acc[nj][3] * a1;
        pd[0] += acc[nj][0] * d0 + acc[nj][1] * d1;
        pd[1] += acc[nj][2] * d0 + acc[nj][3] * d1;
    }
#pragma unroll
    for (int ch = 0; ch < 2; ch++) {
#pragma unroll
        for (int d = 1; d <= 2; d <<= 1) {
            ps[ch] += __shfl_xor_sync(0xffffffffu, ps[ch], d);
            pd[ch] += __shfl_xor_sync(0xffffffffu, pd[ch], d);
        }
    }
    if (lc == 0) {
#pragma unroll
        for (int ch = 0; ch < 2; ch++) {
            int rr = rowBase + mi * 16 + lr + ch * 8;
            if (rr < NN) {
                g_asrc[rr * HEADS + ng] = ps[ch];
                g_adst[rr * HEADS + ng] = pd[ch];
            }
        }
    }
}

// ---------------- scatter + packed per-edge record (MLP-batched) ----------
// Phase order per 4-edge bundle: 8 gathers -> 4 atomics -> exps -> 4 STG.128
__global__ void scatter_alpha_kernel(const int* __restrict__ edges) {
    int t = blockIdx.x * blockDim.x + threadIdx.x;
    if (t >= EE / 4) return;
    int4 s4 = ((const int4*)edges)[t];
    int4 d4 = ((const int4*)(edges + EE))[t];
    int ss[4] = {s4.x, s4.y, s4.z, s4.w};
    int dd[4] = {d4.x, d4.y, d4.z, d4.w};

    float4 as[4], ad[4];
#pragma unroll
    for (int q = 0; q < 4; q++) {
        as[q] = *(const float4*)&g_asrc[ss[q] * HEADS];
        ad[q] = *(const float4*)&g_adst[dd[q] * HEADS];
    }
    int pos[4];
#pragma unroll
    for (int q = 0; q < 4; q++) pos[q] = atomicAdd(&g_cur[dd[q]], 1);

#pragma unroll
    for (int q = 0; q < 4; q++) {
        float e0 = as[q].x + ad[q].x, e1 = as[q].y + ad[q].y;
        float e2 = as[q].z + ad[q].z, e3 = as[q].w + ad[q].w;
        e0 = (e0 > 0.f) ? e0 : NEG_SLOPE * e0;
        e1 = (e1 > 0.f) ? e1 : NEG_SLOPE * e1;
        e2 = (e2 > 0.f) ? e2 : NEG_SLOPE * e2;
        e3 = (e3 > 0.f) ? e3 : NEG_SLOPE * e3;
        __half2 p0 = __floats2half2_rn(__expf(e0), __expf(e1));
        __half2 p1 = __floats2half2_rn(__expf(e2), __expf(e3));
        uint4 rec;
        rec.x = (unsigned)ss[q];
        rec.y = *(unsigned*)&p0;
        rec.z = *(unsigned*)&p1;
        rec.w = 0;
        g_epk[pos[q]] = rec;
    }
}

// ---------------- GAT aggregate: single pass, warp per dst ----------------
__global__ void __launch_bounds__(256) gat_kernel(
        const float* __restrict__ bias, float* __restrict__ out) {
    __shared__ __align__(16) float s_al[8][32][4];
    __shared__ int s_src[8][32];

    const int w = threadIdx.x >> 5;
    const int lane = threadIdx.x & 31;
    const int n = blockIdx.x * 8 + w;
    if (n >= NN) return;

    const int start = g_off[n];
    const int deg   = g_deg[n];
    const int lane4 = lane * 4;
    float4 bv = *(const float4*)&bias[lane4];

    if (deg == 0) {
        *(float4*)&out[n * FOUT + lane4] = bv;
        return;
    }

    const int hl = lane >> 3;
    float4 acc = make_float4(0.f, 0.f, 0.f, 0.f);
    float dacc = 0.f;   // denominator for this lane's head

    for (int base = 0; base < deg; base += 32) {
        int i = base + lane;
        if (i < deg) {
            uint4 rec = g_epk[start + i];     // one LDG.128 per edge
            s_src[w][lane] = (int)rec.x;
            float2 a0 = __half22float2(*(__half2*)&rec.y);
            float2 a1 = __half22float2(*(__half2*)&rec.z);
            s_al[w][lane][0] = a0.x;
            s_al[w][lane][1] = a0.y;
            s_al[w][lane][2] = a1.x;
            s_al[w][lane][3] = a1.y;
        }
        __syncwarp();

        int cnt = min(32, deg - base);
#pragma unroll 8
        for (int j = 0; j < cnt; j++) {
            int sj = s_src[w][j];
            float ex = s_al[w][j][hl];
            dacc += ex;
            uint2 u = *(const uint2*)&g_hh[sj * FOUT + lane4];   // 256B/warp
            float2 f0 = __half22float2(*(__half2*)&u.x);
            float2 f1 = __half22float2(*(__half2*)&u.y);
            acc.x += ex * f0.x;
            acc.y += ex * f0.y;
            acc.z += ex * f1.x;
            acc.w += ex * f1.y;
        }
        __syncwarp();
    }
    float invd = 1.f / fmaxf(dacc, 1e-16f);
    acc.x = acc.x * invd + bv.x;
    acc.y = acc.y * invd + bv.y;
    acc.z = acc.z * invd + bv.z;
    acc.w = acc.w * invd + bv.w;
    *(float4*)&out[n * FOUT + lane4] = acc;
}

// ---------------- launch: forked DAG --------------------------------------
// s0 (capture stream): zero -> hist -> scan1 -> scan2 ──┐
// s2 (forked):         wperm -> gemm ────────────────────┴─> scatter -> gat
extern "C" void kernel_launch(void* const* d_in, const int* in_sizes, int n_in,
                              void* d_out, int out_size) {
    const float* x       = (const float*)d_in[0];
    const int*   edges   = (const int*)d_in[1];    // int32! (JAX x64 disabled)
    const float* W       = (const float*)d_in[2];
    const float* att_src = (const float*)d_in[3];
    const float* att_dst = (const float*)d_in[4];
    const float* bias    = (const float*)d_in[5];
    float*       out     = (float*)d_out;

    cudaFuncSetAttribute(gemm_a_kernel,
                         cudaFuncAttributeMaxDynamicSharedMemorySize, GEMM_SMEM_BYTES);

    cudaStream_t s2;
    cudaStreamCreateWithFlags(&s2, cudaStreamNonBlocking);
    cudaEvent_t evFork, evJoin;
    cudaEventCreateWithFlags(&evFork, cudaEventDisableTiming);
    cudaEventCreateWithFlags(&evJoin, cudaEventDisableTiming);

    // fork s2 off the capture (default) stream
    cudaEventRecord(evFork, 0);
    cudaStreamWaitEvent(s2, evFork, 0);

    // branch A (default stream): CSR build
    zero_kernel<<<(NN + 255) / 256, 256>>>();
    hist_kernel<<<(EE / 2 + 255) / 256, 256>>>(edges);
    // branch B (s2): W permute + GEMM
    wperm_kernel<<<(FIN * FOUT + 255) / 256, 256, 0, s2>>>(W);
    gemm_a_kernel<<<(NN + 63) / 64, 512, GEMM_SMEM_BYTES, s2>>>(x, att_src, att_dst);
    // branch A continues
    scan1_kernel<<<SCAN_BLOCKS, 256>>>();
    scan2_kernel<<<SCAN_BLOCKS, 256>>>();

    // join: default stream waits for gemm
    cudaEventRecord(evJoin, s2);
    cudaStreamWaitEvent(0, evJoin, 0);

    scatter_alpha_kernel<<<(EE / 4 + 255) / 256, 256>>>(edges);
    gat_kernel<<<(NN + 7) / 8, 256>>>(bias, out);
}